// round 10
// baseline (speedup 1.0000x reference)
#include <cuda_runtime.h>
#include <cuda_fp16.h>
#include <cstdint>

// ===========================================================================
// MoE segment-linear via single-term fp16 mma.sync GEMM (fp32 accumulate).
//   y[n,o] = sum_e coeff[seg(n),e] * dot(x[n,:], W[e,o,:]) + bias[o]
// R10: 6-stage BKT=32 pipeline, prefetch distance 4, barrier every 2 chunks
// (relaxed lockstep); W-mix split across 2 block groups.
// ===========================================================================

#define MAX_X_ELEMS (16u * 1024u * 1024u)   // N*I
#define MAX_W_ELEMS (16u * 1024u * 1024u)   // B*O*I
#define MAX_TILES 4096
#define MAX_COEFF 512

__device__ __half g_xh[MAX_X_ELEMS];
__device__ __half g_wh[MAX_W_ELEMS];
__device__ int g_tile_row[MAX_TILES];
__device__ int g_tile_rows[MAX_TILES];
__device__ int g_tile_seg[MAX_TILES];
__device__ int g_tile_cnt;

// ---------------------------------------------------------------------------
// Helpers (baseline PTX only)
// ---------------------------------------------------------------------------
__device__ __forceinline__ uint32_t smem_u32(const void* p) {
    uint32_t a;
    asm("{ .reg .u64 t; cvta.to.shared.u64 t, %1; cvt.u32.u64 %0, t; }"
        : "=r"(a) : "l"(p));
    return a;
}
__device__ __forceinline__ void cp16(uint32_t dst, const void* src, int szbytes) {
    asm volatile("cp.async.cg.shared.global [%0], [%1], 16, %2;"
                 :: "r"(dst), "l"(src), "r"(szbytes));
}
#define CP_COMMIT() asm volatile("cp.async.commit_group;")
#define CP_WAIT(n)  asm volatile("cp.async.wait_group %0;" :: "n"(n))

__device__ __forceinline__ void ldm4(uint32_t* r, uint32_t addr) {
    asm volatile("ldmatrix.sync.aligned.m8n8.x4.shared.b16 {%0,%1,%2,%3}, [%4];"
                 : "=r"(r[0]), "=r"(r[1]), "=r"(r[2]), "=r"(r[3]) : "r"(addr));
}
__device__ __forceinline__ void mma_f16(float* c, const uint32_t* a,
                                        uint32_t b0, uint32_t b1) {
    asm volatile(
        "mma.sync.aligned.m16n8k16.row.col.f32.f16.f16.f32 "
        "{%0,%1,%2,%3}, {%4,%5,%6,%7}, {%8,%9}, {%0,%1,%2,%3};"
        : "+f"(c[0]), "+f"(c[1]), "+f"(c[2]), "+f"(c[3])
        : "r"(a[0]), "r"(a[1]), "r"(a[2]), "r"(a[3]), "r"(b0), "r"(b1));
}

// ---------------------------------------------------------------------------
// Fused prep kernel.
//   blocks [0, xb)        : x -> fp16
//   blocks [xb, xb+2*wb)  : mix W -> fp16 (2 groups of 8 segments each)
//   block  xb+2*wb        : tile table
// ---------------------------------------------------------------------------
#define BMT 128
#define BNT 128
#define BKT 32
#define NSTAGES 6

__global__ void prep_kernel(const float* __restrict__ x,
                            const float* __restrict__ W,
                            const float* __restrict__ coeff,
                            const int* __restrict__ mole_sizes,
                            int E, int B,
                            long long n4, long long OI4, int xb, int wb) {
    int bid = blockIdx.x;
    if (bid < xb) {
        long long idx = (long long)bid * blockDim.x + threadIdx.x;
        if (idx >= n4) return;
        float4 v = reinterpret_cast<const float4*>(x)[idx];
        __half2* h2 = reinterpret_cast<__half2*>(g_xh);
        h2[idx * 2 + 0] = __floats2half2_rn(v.x, v.y);
        h2[idx * 2 + 1] = __floats2half2_rn(v.z, v.w);
        return;
    }
    if (bid < xb + 2 * wb) {
        int grp = (bid - xb) / wb;                 // 0 or 1
        long long idx = (long long)((bid - xb) % wb) * blockDim.x + threadIdx.x;
        __shared__ float sc[MAX_COEFF];
        int ncoef = B * E;
        for (int i = threadIdx.x; i < ncoef; i += blockDim.x) sc[i] = coeff[i];
        __syncthreads();
        if (idx >= OI4) return;

        float4 w[8];
#pragma unroll
        for (int e = 0; e < 8; e++) {
            if (e < E)
                w[e] = reinterpret_cast<const float4*>(W)[(long long)e * OI4 + idx];
            else
                w[e] = make_float4(0.f, 0.f, 0.f, 0.f);
        }
        long long OI = OI4 * 4;
        int b0 = grp * (B / 2);
        int b1 = (grp + 1) * (B / 2);
        for (int b = b0; b < b1; b++) {
            float4 acc = make_float4(0.f, 0.f, 0.f, 0.f);
#pragma unroll
            for (int e = 0; e < 8; e++) {
                if (e < E) {
                    float c = sc[b * E + e];
                    acc.x += c * w[e].x; acc.y += c * w[e].y;
                    acc.z += c * w[e].z; acc.w += c * w[e].w;
                }
            }
            __half2* h2 = reinterpret_cast<__half2*>(g_wh + (long long)b * OI);
            h2[idx * 2 + 0] = __floats2half2_rn(acc.x, acc.y);
            h2[idx * 2 + 1] = __floats2half2_rn(acc.z, acc.w);
        }
        return;
    }
    // tile table
    if (threadIdx.x == 0) {
        int cnt = 0, off = 0;
        for (int b = 0; b < B; b++) {
            int sz = mole_sizes[b];
            for (int r = 0; r < sz; r += BMT) {
                if (cnt < MAX_TILES) {
                    g_tile_row[cnt] = off + r;
                    g_tile_rows[cnt] = (sz - r) < BMT ? (sz - r) : BMT;
                    g_tile_seg[cnt] = b;
                }
                cnt++;
            }
            off += sz;
        }
        g_tile_cnt = cnt < MAX_TILES ? cnt : MAX_TILES;
    }
}

// ---------------------------------------------------------------------------
// GEMM: fp16 mma.sync, 128x128 CTA tile, 4 warps (64x64 each), 2 CTAs/SM.
// 6-stage cp.async pipeline, BKT=32, prefetch distance 4, wait_group(3),
// __syncthreads only on even chunks (stage write (c+4)%6 never collides with
// stages readable inside a 2-chunk barrier window).
// Per stage (16KB): A 8KB | B 8KB. Tile = 128 rows x 64B (4 x 16B chunks),
// swizzle: chunk' = c ^ ((r>>1)&3).
// ---------------------------------------------------------------------------
#define TILE_B   8192
#define STAGE_B  (2 * TILE_B)
#define O_A 0
#define O_B TILE_B
#define GEMM_SMEM (NSTAGES * STAGE_B)
#define GTHREADS 128
#define PF_DIST 4

__device__ __forceinline__ uint32_t swz_off(uint32_t r, uint32_t c) {
    return r * 64u + ((c ^ ((r >> 1) & 3u)) << 4);
}

// one tile = 128 rows x 4 x 16B = 512 cp16; 128 threads -> 4 each
__device__ __forceinline__ void load_tile(uint32_t sdst, const char* gsrc,
                                          long long pitch, int nvalid, int tid) {
#pragma unroll
    for (int t = 0; t < 4; t++) {
        int idx = tid + t * GTHREADS;
        int r = idx >> 2;
        int c = idx & 3;
        uint32_t soff = swz_off((uint32_t)r, (uint32_t)c);
        int rr = r < nvalid ? r : 0;
        int sz = r < nvalid ? 16 : 0;
        cp16(sdst + soff, gsrc + (long long)rr * pitch + c * 16, sz);
    }
}

__global__ __launch_bounds__(GTHREADS, 2)
void gemm_kernel(const float* __restrict__ bias,
                 float* __restrict__ y,
                 int I, int O) {
    int t = blockIdx.y;
    if (t >= g_tile_cnt) return;

    extern __shared__ __align__(1024) char smem[];
    uint32_t sm0 = smem_u32(smem);

    const int tid = threadIdx.x;
    const int lane = tid & 31;
    const int wid = tid >> 5;
    const int warp_m = wid & 1;     // 2 x 64 rows
    const int warp_n = wid >> 1;    // 2 x 64 cols

    const int row0  = g_tile_row[t];
    const int nrows = g_tile_rows[t];
    const int seg   = g_tile_seg[t];
    const int col0  = blockIdx.x * BNT;
    const long long OI = (long long)O * I;
    const long long pitch = (long long)I * 2;   // bytes per row

    const char* wh_base = (const char*)(g_wh + (long long)seg * OI);
    const char* xh_base = (const char*)g_xh;

    int ncols = O - col0;
    if (ncols > BNT) ncols = BNT;

    float acc[4][8][4];
#pragma unroll
    for (int mi = 0; mi < 4; mi++)
#pragma unroll
        for (int nj = 0; nj < 8; nj++)
#pragma unroll
            for (int q = 0; q < 4; q++) acc[mi][nj][q] = 0.f;

    const int nch = I / BKT;   // 32

    // prologue: chunks 0..PF_DIST-1 into stages 0..PF_DIST-1
#pragma unroll
    for (int s = 0; s < PF_DIST; s++) {
        long long kb = (long long)s * 64;   // 32 k-elems * 2B
        uint32_t sb = sm0 + s * STAGE_B;
        load_tile(sb + O_A, xh_base + (long long)row0 * pitch + kb, pitch, nrows, tid);
        load_tile(sb + O_B, wh_base + (long long)col0 * pitch + kb, pitch, ncols, tid);
        CP_COMMIT();
    }

    const int rlA  = ((lane >> 3) & 1) * 8 + (lane & 7);
    const int chiA = lane >> 4;
    const int rlB  = ((lane >> 4) & 1) * 8 + (lane & 7);
    const int chiB = (lane >> 3) & 1;

    for (int c = 0; c < nch; c++) {
        CP_WAIT(3);                 // chunk c complete (<=3 pending newer groups)
        if ((c & 1) == 0) __syncthreads();   // protect stage writes 2 chunks wide

        int pf = c + PF_DIST;
        if (pf < nch) {
            long long kb = (long long)pf * 64;
            uint32_t sb = sm0 + (pf % NSTAGES) * STAGE_B;
            load_tile(sb + O_A, xh_base + (long long)row0 * pitch + kb, pitch, nrows, tid);
            load_tile(sb + O_B, wh_base + (long long)col0 * pitch + kb, pitch, ncols, tid);
        }
        CP_COMMIT();

        uint32_t sb = sm0 + (c % NSTAGES) * STAGE_B;

#pragma unroll
        for (int ks = 0; ks < 2; ks++) {       // 2 x k16 per 32-chunk
            uint32_t a[4][4], b[4][4];
#pragma unroll
            for (int mi = 0; mi < 4; mi++) {
                uint32_t r = (uint32_t)(warp_m * 64 + mi * 16 + rlA);
                ldm4(a[mi], sb + O_A + swz_off(r, (uint32_t)(ks * 2 + chiA)));
            }
#pragma unroll
            for (int g = 0; g < 4; g++) {
                uint32_t r = (uint32_t)(warp_n * 64 + g * 16 + rlB);
                ldm4(b[g], sb + O_B + swz_off(r, (uint32_t)(ks * 2 + chiB)));
            }
#pragma unroll
            for (int mi = 0; mi < 4; mi++)
#pragma unroll
                for (int nj = 0; nj < 8; nj++) {
                    int g = nj >> 1;
                    int p = (nj & 1) * 2;
                    mma_f16(acc[mi][nj], a[mi], b[g][p], b[g][p + 1]);
                }
        }
    }

    // epilogue: add bias, store
#pragma unroll
    for (int mi = 0; mi < 4; mi++) {
        int rA = warp_m * 64 + mi * 16 + (lane >> 2);
        int rB = rA + 8;
#pragma unroll
        for (int nj = 0; nj < 8; nj++) {
            int cg = col0 + warp_n * 64 + nj * 8 + (lane & 3) * 2;
            int cl = cg - col0;
            bool c2 = (cl + 2 <= ncols);
            bool c1 = (cl < ncols);
            float b0 = (cg < O) ? bias[cg] : 0.f;
            float b1 = (cg + 1 < O) ? bias[cg + 1] : 0.f;
            if (rA < nrows) {
                long long base = (long long)(row0 + rA) * O + cg;
                if (c2) {
                    float2 v = make_float2(acc[mi][nj][0] + b0,
                                           acc[mi][nj][1] + b1);
                    *reinterpret_cast<float2*>(y + base) = v;
                } else if (c1) {
                    y[base] = acc[mi][nj][0] + b0;
                }
            }
            if (rB < nrows) {
                long long base = (long long)(row0 + rB) * O + cg;
                if (c2) {
                    float2 v = make_float2(acc[mi][nj][2] + b0,
                                           acc[mi][nj][3] + b1);
                    *reinterpret_cast<float2*>(y + base) = v;
                } else if (c1) {
                    y[base] = acc[mi][nj][2] + b0;
                }
            }
        }
    }
}

// ---------------------------------------------------------------------------
// Launch
// ---------------------------------------------------------------------------
extern "C" void kernel_launch(void* const* d_in, const int* in_sizes, int n_in,
                              void* d_out, int out_size) {
    const float* x     = (const float*)d_in[0];   // [N, I]
    const float* W     = (const float*)d_in[1];   // [E, O, I]
    const float* bias  = (const float*)d_in[2];   // [O]
    const float* coeff = (const float*)d_in[3];   // [B, E]
    const int*   msize = (const int*)  d_in[4];   // [B]

    const int O = in_sizes[2];
    const int N = out_size / O;
    const int I = in_sizes[0] / N;
    const int E = in_sizes[1] / (O * I);
    const int B = in_sizes[3] / E;

    // fused prep
    {
        long long n4 = (long long)N * I / 4;
        long long OI4 = (long long)O * I / 4;
        int threads = 256;
        int xb = (int)((n4 + threads - 1) / threads);
        int wb = (int)((OI4 + threads - 1) / threads);
        prep_kernel<<<xb + 2 * wb + 1, threads>>>(x, W, coeff, msize,
                                                  E, B, n4, OI4, xb, wb);
    }

    // GEMM
    {
        static bool attr_set = false;
        if (!attr_set) {
            cudaFuncSetAttribute(gemm_kernel,
                                 cudaFuncAttributeMaxDynamicSharedMemorySize,
                                 GEMM_SMEM);
            attr_set = true;
        }
        int maxTiles = (N + BMT - 1) / BMT + B;
        dim3 grid((O + BNT - 1) / BNT, maxTiles);
        gemm_kernel<<<grid, GTHREADS, GEMM_SMEM>>>(bias, (float*)d_out, I, O);
    }
}

// round 11
// speedup vs baseline: 1.0927x; 1.0927x over previous
#include <cuda_runtime.h>
#include <cuda_fp16.h>
#include <cstdint>

// ===========================================================================
// MoE segment-linear via single-term fp16 mma.sync GEMM (fp32 accumulate).
//   y[n,o] = sum_e coeff[seg(n),e] * dot(x[n,:], W[e,o,:]) + bias[o]
// R11: GEMM = exact R9 config (best: BKT=64, 3 stages, 4 warps 64x64, 2 CTA/SM).
//      Prep vectorized: 8 elems/thread, 16B uint4 stores on both paths.
// ===========================================================================

#define MAX_X_ELEMS (16u * 1024u * 1024u)   // N*I
#define MAX_W_ELEMS (16u * 1024u * 1024u)   // B*O*I
#define MAX_TILES 4096
#define MAX_COEFF 512

__device__ __half g_xh[MAX_X_ELEMS];
__device__ __half g_wh[MAX_W_ELEMS];
__device__ int g_tile_row[MAX_TILES];
__device__ int g_tile_rows[MAX_TILES];
__device__ int g_tile_seg[MAX_TILES];
__device__ int g_tile_cnt;

// ---------------------------------------------------------------------------
// Helpers (baseline PTX only)
// ---------------------------------------------------------------------------
__device__ __forceinline__ uint32_t smem_u32(const void* p) {
    uint32_t a;
    asm("{ .reg .u64 t; cvta.to.shared.u64 t, %1; cvt.u32.u64 %0, t; }"
        : "=r"(a) : "l"(p));
    return a;
}
__device__ __forceinline__ void cp16(uint32_t dst, const void* src, int szbytes) {
    asm volatile("cp.async.cg.shared.global [%0], [%1], 16, %2;"
                 :: "r"(dst), "l"(src), "r"(szbytes));
}
#define CP_COMMIT() asm volatile("cp.async.commit_group;")
#define CP_WAIT(n)  asm volatile("cp.async.wait_group %0;" :: "n"(n))

__device__ __forceinline__ void ldm4(uint32_t* r, uint32_t addr) {
    asm volatile("ldmatrix.sync.aligned.m8n8.x4.shared.b16 {%0,%1,%2,%3}, [%4];"
                 : "=r"(r[0]), "=r"(r[1]), "=r"(r[2]), "=r"(r[3]) : "r"(addr));
}
__device__ __forceinline__ void mma_f16(float* c, const uint32_t* a,
                                        uint32_t b0, uint32_t b1) {
    asm volatile(
        "mma.sync.aligned.m16n8k16.row.col.f32.f16.f16.f32 "
        "{%0,%1,%2,%3}, {%4,%5,%6,%7}, {%8,%9}, {%0,%1,%2,%3};"
        : "+f"(c[0]), "+f"(c[1]), "+f"(c[2]), "+f"(c[3])
        : "r"(a[0]), "r"(a[1]), "r"(a[2]), "r"(a[3]), "r"(b0), "r"(b1));
}

__device__ __forceinline__ uint4 pack8_f16(const float4& a, const float4& b) {
    union { __half2 h[4]; uint4 u; } r;
    r.h[0] = __floats2half2_rn(a.x, a.y);
    r.h[1] = __floats2half2_rn(a.z, a.w);
    r.h[2] = __floats2half2_rn(b.x, b.y);
    r.h[3] = __floats2half2_rn(b.z, b.w);
    return r.u;
}

// ---------------------------------------------------------------------------
// Fused prep kernel (vectorized: 8 elements per thread, 16B stores).
//   blocks [0, xb)     : x -> fp16
//   blocks [xb, xb+wb) : mix W -> fp16
//   block  xb+wb       : tile table
// ---------------------------------------------------------------------------
#define BMT 128
#define BNT 128
#define BKT 64
#define NSTAGES 3

__global__ void prep_kernel(const float* __restrict__ x,
                            const float* __restrict__ W,
                            const float* __restrict__ coeff,
                            const int* __restrict__ mole_sizes,
                            int E, int B,
                            long long n8, long long OI8, int xb, int wb) {
    int bid = blockIdx.x;
    if (bid < xb) {
        long long idx = (long long)bid * blockDim.x + threadIdx.x;
        if (idx >= n8) return;
        float4 v0 = reinterpret_cast<const float4*>(x)[idx * 2 + 0];
        float4 v1 = reinterpret_cast<const float4*>(x)[idx * 2 + 1];
        reinterpret_cast<uint4*>(g_xh)[idx] = pack8_f16(v0, v1);
        return;
    }
    if (bid < xb + wb) {
        long long idx = (long long)(bid - xb) * blockDim.x + threadIdx.x;
        __shared__ float sc[MAX_COEFF];
        int ncoef = B * E;
        for (int i = threadIdx.x; i < ncoef; i += blockDim.x) sc[i] = coeff[i];
        __syncthreads();
        if (idx >= OI8) return;

        float4 w0[8], w1[8];
#pragma unroll
        for (int e = 0; e < 8; e++) {
            if (e < E) {
                w0[e] = reinterpret_cast<const float4*>(W)[((long long)e * OI8 + idx) * 2 + 0];
                w1[e] = reinterpret_cast<const float4*>(W)[((long long)e * OI8 + idx) * 2 + 1];
            } else {
                w0[e] = make_float4(0.f, 0.f, 0.f, 0.f);
                w1[e] = make_float4(0.f, 0.f, 0.f, 0.f);
            }
        }
        long long OI8b = OI8;   // uint4 elements per segment
        for (int b = 0; b < B; b++) {
            float4 a0 = make_float4(0.f, 0.f, 0.f, 0.f);
            float4 a1 = make_float4(0.f, 0.f, 0.f, 0.f);
#pragma unroll
            for (int e = 0; e < 8; e++) {
                if (e < E) {
                    float c = sc[b * E + e];
                    a0.x += c * w0[e].x; a0.y += c * w0[e].y;
                    a0.z += c * w0[e].z; a0.w += c * w0[e].w;
                    a1.x += c * w1[e].x; a1.y += c * w1[e].y;
                    a1.z += c * w1[e].z; a1.w += c * w1[e].w;
                }
            }
            reinterpret_cast<uint4*>(g_wh)[(long long)b * OI8b + idx] =
                pack8_f16(a0, a1);
        }
        return;
    }
    // tile table
    if (threadIdx.x == 0) {
        int cnt = 0, off = 0;
        for (int b = 0; b < B; b++) {
            int sz = mole_sizes[b];
            for (int r = 0; r < sz; r += BMT) {
                if (cnt < MAX_TILES) {
                    g_tile_row[cnt] = off + r;
                    g_tile_rows[cnt] = (sz - r) < BMT ? (sz - r) : BMT;
                    g_tile_seg[cnt] = b;
                }
                cnt++;
            }
            off += sz;
        }
        g_tile_cnt = cnt < MAX_TILES ? cnt : MAX_TILES;
    }
}

// ---------------------------------------------------------------------------
// GEMM (exact R9): fp16 mma.sync, 128x128 CTA tile, BKT=64, 3-stage pipeline,
// 2 CTAs/SM, 128 threads (4 warps, 2x2 grid), warp tile 64x64.
// Per stage (32KB): A 16KB | B 16KB. Tile = 128 rows x 128B (8 x 16B chunks).
// Swizzle: chunk' = c ^ (r & 7).
// ---------------------------------------------------------------------------
#define TILE_B   16384
#define STAGE_B  (2 * TILE_B)
#define O_A 0
#define O_B TILE_B
#define GEMM_SMEM (NSTAGES * STAGE_B)
#define GTHREADS 128

__device__ __forceinline__ uint32_t swz8(uint32_t r, uint32_t c) {
    return r * 128u + ((c ^ (r & 7u)) << 4);
}

// one tile = 128 rows x 8 x 16B = 1024 cp16; 128 threads -> 8 each
__device__ __forceinline__ void load_tile(uint32_t sdst, const char* gsrc,
                                          long long pitch, int nvalid, int tid) {
#pragma unroll
    for (int t = 0; t < 8; t++) {
        int idx = tid + t * GTHREADS;
        int r = idx >> 3;
        int c = idx & 7;
        uint32_t soff = swz8((uint32_t)r, (uint32_t)c);
        int rr = r < nvalid ? r : 0;
        int sz = r < nvalid ? 16 : 0;
        cp16(sdst + soff, gsrc + (long long)rr * pitch + c * 16, sz);
    }
}

__global__ __launch_bounds__(GTHREADS, 2)
void gemm_kernel(const float* __restrict__ bias,
                 float* __restrict__ y,
                 int I, int O) {
    int t = blockIdx.y;
    if (t >= g_tile_cnt) return;

    extern __shared__ __align__(1024) char smem[];
    uint32_t sm0 = smem_u32(smem);

    const int tid = threadIdx.x;
    const int lane = tid & 31;
    const int wid = tid >> 5;
    const int warp_m = wid & 1;     // 2 x 64 rows
    const int warp_n = wid >> 1;    // 2 x 64 cols

    const int row0  = g_tile_row[t];
    const int nrows = g_tile_rows[t];
    const int seg   = g_tile_seg[t];
    const int col0  = blockIdx.x * BNT;
    const long long OI = (long long)O * I;
    const long long pitch = (long long)I * 2;   // bytes per row

    const char* wh_base = (const char*)(g_wh + (long long)seg * OI);
    const char* xh_base = (const char*)g_xh;

    int ncols = O - col0;
    if (ncols > BNT) ncols = BNT;

    float acc[4][8][4];
#pragma unroll
    for (int mi = 0; mi < 4; mi++)
#pragma unroll
        for (int nj = 0; nj < 8; nj++)
#pragma unroll
            for (int q = 0; q < 4; q++) acc[mi][nj][q] = 0.f;

    const int nch = I / BKT;   // 16

#pragma unroll
    for (int s = 0; s < NSTAGES - 1; s++) {
        long long kb = (long long)s * 128;  // 64 k-elems * 2B
        uint32_t sb = sm0 + s * STAGE_B;
        load_tile(sb + O_A, xh_base + (long long)row0 * pitch + kb, pitch, nrows, tid);
        load_tile(sb + O_B, wh_base + (long long)col0 * pitch + kb, pitch, ncols, tid);
        CP_COMMIT();
    }

    const int rlA  = ((lane >> 3) & 1) * 8 + (lane & 7);
    const int chiA = lane >> 4;
    const int rlB  = ((lane >> 4) & 1) * 8 + (lane & 7);
    const int chiB = (lane >> 3) & 1;

    for (int c = 0; c < nch; c++) {
        CP_WAIT(NSTAGES - 2);
        __syncthreads();

        int pf = c + NSTAGES - 1;
        if (pf < nch) {
            long long kb = (long long)pf * 128;
            uint32_t sb = sm0 + (pf % NSTAGES) * STAGE_B;
            load_tile(sb + O_A, xh_base + (long long)row0 * pitch + kb, pitch, nrows, tid);
            load_tile(sb + O_B, wh_base + (long long)col0 * pitch + kb, pitch, ncols, tid);
        }
        CP_COMMIT();

        uint32_t sb = sm0 + (c % NSTAGES) * STAGE_B;

#pragma unroll
        for (int ks = 0; ks < 4; ks++) {       // 4 x k16 per 64-chunk
            uint32_t a[4][4], b[4][4];
#pragma unroll
            for (int mi = 0; mi < 4; mi++) {
                uint32_t r = (uint32_t)(warp_m * 64 + mi * 16 + rlA);
                ldm4(a[mi], sb + O_A + swz8(r, (uint32_t)(ks * 2 + chiA)));
            }
#pragma unroll
            for (int g = 0; g < 4; g++) {
                uint32_t r = (uint32_t)(warp_n * 64 + g * 16 + rlB);
                ldm4(b[g], sb + O_B + swz8(r, (uint32_t)(ks * 2 + chiB)));
            }
#pragma unroll
            for (int mi = 0; mi < 4; mi++)
#pragma unroll
                for (int nj = 0; nj < 8; nj++) {
                    int g = nj >> 1;
                    int p = (nj & 1) * 2;
                    mma_f16(acc[mi][nj], a[mi], b[g][p], b[g][p + 1]);
                }
        }
    }

    // epilogue: add bias, store
#pragma unroll
    for (int mi = 0; mi < 4; mi++) {
        int rA = warp_m * 64 + mi * 16 + (lane >> 2);
        int rB = rA + 8;
#pragma unroll
        for (int nj = 0; nj < 8; nj++) {
            int cg = col0 + warp_n * 64 + nj * 8 + (lane & 3) * 2;
            int cl = cg - col0;
            bool c2 = (cl + 2 <= ncols);
            bool c1 = (cl < ncols);
            float b0 = (cg < O) ? bias[cg] : 0.f;
            float b1 = (cg + 1 < O) ? bias[cg + 1] : 0.f;
            if (rA < nrows) {
                long long base = (long long)(row0 + rA) * O + cg;
                if (c2) {
                    float2 v = make_float2(acc[mi][nj][0] + b0,
                                           acc[mi][nj][1] + b1);
                    *reinterpret_cast<float2*>(y + base) = v;
                } else if (c1) {
                    y[base] = acc[mi][nj][0] + b0;
                }
            }
            if (rB < nrows) {
                long long base = (long long)(row0 + rB) * O + cg;
                if (c2) {
                    float2 v = make_float2(acc[mi][nj][2] + b0,
                                           acc[mi][nj][3] + b1);
                    *reinterpret_cast<float2*>(y + base) = v;
                } else if (c1) {
                    y[base] = acc[mi][nj][2] + b0;
                }
            }
        }
    }
}

// ---------------------------------------------------------------------------
// Launch
// ---------------------------------------------------------------------------
extern "C" void kernel_launch(void* const* d_in, const int* in_sizes, int n_in,
                              void* d_out, int out_size) {
    const float* x     = (const float*)d_in[0];   // [N, I]
    const float* W     = (const float*)d_in[1];   // [E, O, I]
    const float* bias  = (const float*)d_in[2];   // [O]
    const float* coeff = (const float*)d_in[3];   // [B, E]
    const int*   msize = (const int*)  d_in[4];   // [B]

    const int O = in_sizes[2];
    const int N = out_size / O;
    const int I = in_sizes[0] / N;
    const int E = in_sizes[1] / (O * I);
    const int B = in_sizes[3] / E;

    // fused prep (vectorized: 8 elems per thread)
    {
        long long n8 = (long long)N * I / 8;
        long long OI8 = (long long)O * I / 8;
        int threads = 256;
        int xb = (int)((n8 + threads - 1) / threads);
        int wb = (int)((OI8 + threads - 1) / threads);
        prep_kernel<<<xb + wb + 1, threads>>>(x, W, coeff, msize,
                                              E, B, n8, OI8, xb, wb);
    }

    // GEMM
    {
        static bool attr_set = false;
        if (!attr_set) {
            cudaFuncSetAttribute(gemm_kernel,
                                 cudaFuncAttributeMaxDynamicSharedMemorySize,
                                 GEMM_SMEM);
            attr_set = true;
        }
        int maxTiles = (N + BMT - 1) / BMT + B;
        dim3 grid((O + BNT - 1) / BNT, maxTiles);
        gemm_kernel<<<grid, GTHREADS, GEMM_SMEM>>>(bias, (float*)d_out, I, O);
    }
}

// round 12
// speedup vs baseline: 1.1108x; 1.0166x over previous
#include <cuda_runtime.h>
#include <cuda_fp16.h>
#include <cstdint>

// ===========================================================================
// MoE segment-linear via single-term fp16 mma.sync GEMM (fp32 accumulate).
//   y[n,o] = sum_e coeff[seg(n),e] * dot(x[n,:], W[e,o,:]) + bias[o]
// R12: R11 + L2 cache-policy hints:
//   - prep reads fp32 x/W with __ldcs (evict-first; don't evict fp16 outputs)
//   - gemm y stores with st.global.cs (streaming; keep operands L2-resident)
// GEMM core = proven R9 config (BKT=64, 3 stages, 4 warps 64x64, 2 CTA/SM).
// ===========================================================================

#define MAX_X_ELEMS (16u * 1024u * 1024u)   // N*I
#define MAX_W_ELEMS (16u * 1024u * 1024u)   // B*O*I
#define MAX_TILES 4096
#define MAX_COEFF 512

__device__ __half g_xh[MAX_X_ELEMS];
__device__ __half g_wh[MAX_W_ELEMS];
__device__ int g_tile_row[MAX_TILES];
__device__ int g_tile_rows[MAX_TILES];
__device__ int g_tile_seg[MAX_TILES];
__device__ int g_tile_cnt;

// ---------------------------------------------------------------------------
// Helpers (baseline PTX only)
// ---------------------------------------------------------------------------
__device__ __forceinline__ uint32_t smem_u32(const void* p) {
    uint32_t a;
    asm("{ .reg .u64 t; cvta.to.shared.u64 t, %1; cvt.u32.u64 %0, t; }"
        : "=r"(a) : "l"(p));
    return a;
}
__device__ __forceinline__ void cp16(uint32_t dst, const void* src, int szbytes) {
    asm volatile("cp.async.cg.shared.global [%0], [%1], 16, %2;"
                 :: "r"(dst), "l"(src), "r"(szbytes));
}
#define CP_COMMIT() asm volatile("cp.async.commit_group;")
#define CP_WAIT(n)  asm volatile("cp.async.wait_group %0;" :: "n"(n))

__device__ __forceinline__ void ldm4(uint32_t* r, uint32_t addr) {
    asm volatile("ldmatrix.sync.aligned.m8n8.x4.shared.b16 {%0,%1,%2,%3}, [%4];"
                 : "=r"(r[0]), "=r"(r[1]), "=r"(r[2]), "=r"(r[3]) : "r"(addr));
}
__device__ __forceinline__ void mma_f16(float* c, const uint32_t* a,
                                        uint32_t b0, uint32_t b1) {
    asm volatile(
        "mma.sync.aligned.m16n8k16.row.col.f32.f16.f16.f32 "
        "{%0,%1,%2,%3}, {%4,%5,%6,%7}, {%8,%9}, {%0,%1,%2,%3};"
        : "+f"(c[0]), "+f"(c[1]), "+f"(c[2]), "+f"(c[3])
        : "r"(a[0]), "r"(a[1]), "r"(a[2]), "r"(a[3]), "r"(b0), "r"(b1));
}

__device__ __forceinline__ void stcs2(float* p, float v0, float v1) {
    asm volatile("st.global.cs.v2.f32 [%0], {%1, %2};"
                 :: "l"(p), "f"(v0), "f"(v1) : "memory");
}
__device__ __forceinline__ void stcs1(float* p, float v0) {
    asm volatile("st.global.cs.f32 [%0], %1;" :: "l"(p), "f"(v0) : "memory");
}

__device__ __forceinline__ uint4 pack8_f16(const float4& a, const float4& b) {
    union { __half2 h[4]; uint4 u; } r;
    r.h[0] = __floats2half2_rn(a.x, a.y);
    r.h[1] = __floats2half2_rn(a.z, a.w);
    r.h[2] = __floats2half2_rn(b.x, b.y);
    r.h[3] = __floats2half2_rn(b.z, b.w);
    return r.u;
}

// ---------------------------------------------------------------------------
// Fused prep kernel (vectorized; fp32 inputs read with __ldcs = evict-first).
//   blocks [0, xb)     : x -> fp16
//   blocks [xb, xb+wb) : mix W -> fp16
//   block  xb+wb       : tile table
// ---------------------------------------------------------------------------
#define BMT 128
#define BNT 128
#define BKT 64
#define NSTAGES 3

__global__ void prep_kernel(const float* __restrict__ x,
                            const float* __restrict__ W,
                            const float* __restrict__ coeff,
                            const int* __restrict__ mole_sizes,
                            int E, int B,
                            long long n8, long long OI8, int xb, int wb) {
    int bid = blockIdx.x;
    if (bid < xb) {
        long long idx = (long long)bid * blockDim.x + threadIdx.x;
        if (idx >= n8) return;
        float4 v0 = __ldcs(reinterpret_cast<const float4*>(x) + idx * 2 + 0);
        float4 v1 = __ldcs(reinterpret_cast<const float4*>(x) + idx * 2 + 1);
        reinterpret_cast<uint4*>(g_xh)[idx] = pack8_f16(v0, v1);
        return;
    }
    if (bid < xb + wb) {
        long long idx = (long long)(bid - xb) * blockDim.x + threadIdx.x;
        __shared__ float sc[MAX_COEFF];
        int ncoef = B * E;
        for (int i = threadIdx.x; i < ncoef; i += blockDim.x) sc[i] = coeff[i];
        __syncthreads();
        if (idx >= OI8) return;

        float4 w0[8], w1[8];
#pragma unroll
        for (int e = 0; e < 8; e++) {
            if (e < E) {
                w0[e] = __ldcs(reinterpret_cast<const float4*>(W)
                               + ((long long)e * OI8 + idx) * 2 + 0);
                w1[e] = __ldcs(reinterpret_cast<const float4*>(W)
                               + ((long long)e * OI8 + idx) * 2 + 1);
            } else {
                w0[e] = make_float4(0.f, 0.f, 0.f, 0.f);
                w1[e] = make_float4(0.f, 0.f, 0.f, 0.f);
            }
        }
        for (int b = 0; b < B; b++) {
            float4 a0 = make_float4(0.f, 0.f, 0.f, 0.f);
            float4 a1 = make_float4(0.f, 0.f, 0.f, 0.f);
#pragma unroll
            for (int e = 0; e < 8; e++) {
                if (e < E) {
                    float c = sc[b * E + e];
                    a0.x += c * w0[e].x; a0.y += c * w0[e].y;
                    a0.z += c * w0[e].z; a0.w += c * w0[e].w;
                    a1.x += c * w1[e].x; a1.y += c * w1[e].y;
                    a1.z += c * w1[e].z; a1.w += c * w1[e].w;
                }
            }
            reinterpret_cast<uint4*>(g_wh)[(long long)b * OI8 + idx] =
                pack8_f16(a0, a1);
        }
        return;
    }
    // tile table
    if (threadIdx.x == 0) {
        int cnt = 0, off = 0;
        for (int b = 0; b < B; b++) {
            int sz = mole_sizes[b];
            for (int r = 0; r < sz; r += BMT) {
                if (cnt < MAX_TILES) {
                    g_tile_row[cnt] = off + r;
                    g_tile_rows[cnt] = (sz - r) < BMT ? (sz - r) : BMT;
                    g_tile_seg[cnt] = b;
                }
                cnt++;
            }
            off += sz;
        }
        g_tile_cnt = cnt < MAX_TILES ? cnt : MAX_TILES;
    }
}

// ---------------------------------------------------------------------------
// GEMM (R9 core): fp16 mma.sync, 128x128 CTA tile, BKT=64, 3-stage pipeline,
// 2 CTAs/SM, 128 threads (4 warps, 2x2 grid), warp tile 64x64.
// Per stage (32KB): A 16KB | B 16KB. Tile = 128 rows x 128B (8 x 16B chunks).
// Swizzle: chunk' = c ^ (r & 7).  Epilogue y stores are streaming (.cs).
// ---------------------------------------------------------------------------
#define TILE_B   16384
#define STAGE_B  (2 * TILE_B)
#define O_A 0
#define O_B TILE_B
#define GEMM_SMEM (NSTAGES * STAGE_B)
#define GTHREADS 128

__device__ __forceinline__ uint32_t swz8(uint32_t r, uint32_t c) {
    return r * 128u + ((c ^ (r & 7u)) << 4);
}

// one tile = 128 rows x 8 x 16B = 1024 cp16; 128 threads -> 8 each
__device__ __forceinline__ void load_tile(uint32_t sdst, const char* gsrc,
                                          long long pitch, int nvalid, int tid) {
#pragma unroll
    for (int t = 0; t < 8; t++) {
        int idx = tid + t * GTHREADS;
        int r = idx >> 3;
        int c = idx & 7;
        uint32_t soff = swz8((uint32_t)r, (uint32_t)c);
        int rr = r < nvalid ? r : 0;
        int sz = r < nvalid ? 16 : 0;
        cp16(sdst + soff, gsrc + (long long)rr * pitch + c * 16, sz);
    }
}

__global__ __launch_bounds__(GTHREADS, 2)
void gemm_kernel(const float* __restrict__ bias,
                 float* __restrict__ y,
                 int I, int O) {
    int t = blockIdx.y;
    if (t >= g_tile_cnt) return;

    extern __shared__ __align__(1024) char smem[];
    uint32_t sm0 = smem_u32(smem);

    const int tid = threadIdx.x;
    const int lane = tid & 31;
    const int wid = tid >> 5;
    const int warp_m = wid & 1;     // 2 x 64 rows
    const int warp_n = wid >> 1;    // 2 x 64 cols

    const int row0  = g_tile_row[t];
    const int nrows = g_tile_rows[t];
    const int seg   = g_tile_seg[t];
    const int col0  = blockIdx.x * BNT;
    const long long OI = (long long)O * I;
    const long long pitch = (long long)I * 2;   // bytes per row

    const char* wh_base = (const char*)(g_wh + (long long)seg * OI);
    const char* xh_base = (const char*)g_xh;

    int ncols = O - col0;
    if (ncols > BNT) ncols = BNT;

    float acc[4][8][4];
#pragma unroll
    for (int mi = 0; mi < 4; mi++)
#pragma unroll
        for (int nj = 0; nj < 8; nj++)
#pragma unroll
            for (int q = 0; q < 4; q++) acc[mi][nj][q] = 0.f;

    const int nch = I / BKT;   // 16

#pragma unroll
    for (int s = 0; s < NSTAGES - 1; s++) {
        long long kb = (long long)s * 128;  // 64 k-elems * 2B
        uint32_t sb = sm0 + s * STAGE_B;
        load_tile(sb + O_A, xh_base + (long long)row0 * pitch + kb, pitch, nrows, tid);
        load_tile(sb + O_B, wh_base + (long long)col0 * pitch + kb, pitch, ncols, tid);
        CP_COMMIT();
    }

    const int rlA  = ((lane >> 3) & 1) * 8 + (lane & 7);
    const int chiA = lane >> 4;
    const int rlB  = ((lane >> 4) & 1) * 8 + (lane & 7);
    const int chiB = (lane >> 3) & 1;

    for (int c = 0; c < nch; c++) {
        CP_WAIT(NSTAGES - 2);
        __syncthreads();

        int pf = c + NSTAGES - 1;
        if (pf < nch) {
            long long kb = (long long)pf * 128;
            uint32_t sb = sm0 + (pf % NSTAGES) * STAGE_B;
            load_tile(sb + O_A, xh_base + (long long)row0 * pitch + kb, pitch, nrows, tid);
            load_tile(sb + O_B, wh_base + (long long)col0 * pitch + kb, pitch, ncols, tid);
        }
        CP_COMMIT();

        uint32_t sb = sm0 + (c % NSTAGES) * STAGE_B;

#pragma unroll
        for (int ks = 0; ks < 4; ks++) {       // 4 x k16 per 64-chunk
            uint32_t a[4][4], b[4][4];
#pragma unroll
            for (int mi = 0; mi < 4; mi++) {
                uint32_t r = (uint32_t)(warp_m * 64 + mi * 16 + rlA);
                ldm4(a[mi], sb + O_A + swz8(r, (uint32_t)(ks * 2 + chiA)));
            }
#pragma unroll
            for (int g = 0; g < 4; g++) {
                uint32_t r = (uint32_t)(warp_n * 64 + g * 16 + rlB);
                ldm4(b[g], sb + O_B + swz8(r, (uint32_t)(ks * 2 + chiB)));
            }
#pragma unroll
            for (int mi = 0; mi < 4; mi++)
#pragma unroll
                for (int nj = 0; nj < 8; nj++) {
                    int g = nj >> 1;
                    int p = (nj & 1) * 2;
                    mma_f16(acc[mi][nj], a[mi], b[g][p], b[g][p + 1]);
                }
        }
    }

    // epilogue: add bias, store y with streaming hint (.cs)
#pragma unroll
    for (int mi = 0; mi < 4; mi++) {
        int rA = warp_m * 64 + mi * 16 + (lane >> 2);
        int rB = rA + 8;
#pragma unroll
        for (int nj = 0; nj < 8; nj++) {
            int cg = col0 + warp_n * 64 + nj * 8 + (lane & 3) * 2;
            int cl = cg - col0;
            bool c2 = (cl + 2 <= ncols);
            bool c1 = (cl < ncols);
            float b0 = (cg < O) ? bias[cg] : 0.f;
            float b1 = (cg + 1 < O) ? bias[cg + 1] : 0.f;
            if (rA < nrows) {
                long long base = (long long)(row0 + rA) * O + cg;
                if (c2) {
                    stcs2(y + base, acc[mi][nj][0] + b0, acc[mi][nj][1] + b1);
                } else if (c1) {
                    stcs1(y + base, acc[mi][nj][0] + b0);
                }
            }
            if (rB < nrows) {
                long long base = (long long)(row0 + rB) * O + cg;
                if (c2) {
                    stcs2(y + base, acc[mi][nj][2] + b0, acc[mi][nj][3] + b1);
                } else if (c1) {
                    stcs1(y + base, acc[mi][nj][2] + b0);
                }
            }
        }
    }
}

// ---------------------------------------------------------------------------
// Launch
// ---------------------------------------------------------------------------
extern "C" void kernel_launch(void* const* d_in, const int* in_sizes, int n_in,
                              void* d_out, int out_size) {
    const float* x     = (const float*)d_in[0];   // [N, I]
    const float* W     = (const float*)d_in[1];   // [E, O, I]
    const float* bias  = (const float*)d_in[2];   // [O]
    const float* coeff = (const float*)d_in[3];   // [B, E]
    const int*   msize = (const int*)  d_in[4];   // [B]

    const int O = in_sizes[2];
    const int N = out_size / O;
    const int I = in_sizes[0] / N;
    const int E = in_sizes[1] / (O * I);
    const int B = in_sizes[3] / E;

    // fused prep (vectorized: 8 elems per thread)
    {
        long long n8 = (long long)N * I / 8;
        long long OI8 = (long long)O * I / 8;
        int threads = 256;
        int xb = (int)((n8 + threads - 1) / threads);
        int wb = (int)((OI8 + threads - 1) / threads);
        prep_kernel<<<xb + wb + 1, threads>>>(x, W, coeff, msize,
                                              E, B, n8, OI8, xb, wb);
    }

    // GEMM
    {
        static bool attr_set = false;
        if (!attr_set) {
            cudaFuncSetAttribute(gemm_kernel,
                                 cudaFuncAttributeMaxDynamicSharedMemorySize,
                                 GEMM_SMEM);
            attr_set = true;
        }
        int maxTiles = (N + BMT - 1) / BMT + B;
        dim3 grid((O + BNT - 1) / BNT, maxTiles);
        gemm_kernel<<<grid, GTHREADS, GEMM_SMEM>>>(bias, (float*)d_out, I, O);
    }
}

// round 13
// speedup vs baseline: 1.1130x; 1.0020x over previous
#include <cuda_runtime.h>
#include <cuda_fp16.h>
#include <cstdint>

// ===========================================================================
// MoE segment-linear via single-term fp16 mma.sync GEMM (fp32 accumulate).
//   y[n,o] = sum_e coeff[seg(n),e] * dot(x[n,:], W[e,o,:]) + bias[o]
// R13: persistent GEMM (grid ~2/SM), continuous cp.async K-stream across
// work items (no per-tile pipeline fill/drain; epilogue overlapped with the
// next item's prefetch). Core geometry = proven R9 (BKT=64, 3 stages,
// 4 warps 64x64, 2 CTA/SM). Prep = R12 (vectorized + __ldcs).
// ===========================================================================

#define MAX_X_ELEMS (16u * 1024u * 1024u)   // N*I
#define MAX_W_ELEMS (16u * 1024u * 1024u)   // B*O*I
#define MAX_TILES 4096
#define MAX_COEFF 512

__device__ __half g_xh[MAX_X_ELEMS];
__device__ __half g_wh[MAX_W_ELEMS];
__device__ int g_tile_row[MAX_TILES];
__device__ int g_tile_rows[MAX_TILES];
__device__ int g_tile_seg[MAX_TILES];
__device__ int g_tile_cnt;

// ---------------------------------------------------------------------------
// Helpers (baseline PTX only)
// ---------------------------------------------------------------------------
__device__ __forceinline__ uint32_t smem_u32(const void* p) {
    uint32_t a;
    asm("{ .reg .u64 t; cvta.to.shared.u64 t, %1; cvt.u32.u64 %0, t; }"
        : "=r"(a) : "l"(p));
    return a;
}
__device__ __forceinline__ void cp16(uint32_t dst, const void* src, int szbytes) {
    asm volatile("cp.async.cg.shared.global [%0], [%1], 16, %2;"
                 :: "r"(dst), "l"(src), "r"(szbytes));
}
#define CP_COMMIT() asm volatile("cp.async.commit_group;")
#define CP_WAIT(n)  asm volatile("cp.async.wait_group %0;" :: "n"(n))

__device__ __forceinline__ void ldm4(uint32_t* r, uint32_t addr) {
    asm volatile("ldmatrix.sync.aligned.m8n8.x4.shared.b16 {%0,%1,%2,%3}, [%4];"
                 : "=r"(r[0]), "=r"(r[1]), "=r"(r[2]), "=r"(r[3]) : "r"(addr));
}
__device__ __forceinline__ void mma_f16(float* c, const uint32_t* a,
                                        uint32_t b0, uint32_t b1) {
    asm volatile(
        "mma.sync.aligned.m16n8k16.row.col.f32.f16.f16.f32 "
        "{%0,%1,%2,%3}, {%4,%5,%6,%7}, {%8,%9}, {%0,%1,%2,%3};"
        : "+f"(c[0]), "+f"(c[1]), "+f"(c[2]), "+f"(c[3])
        : "r"(a[0]), "r"(a[1]), "r"(a[2]), "r"(a[3]), "r"(b0), "r"(b1));
}
__device__ __forceinline__ void stcs2(float* p, float v0, float v1) {
    asm volatile("st.global.cs.v2.f32 [%0], {%1, %2};"
                 :: "l"(p), "f"(v0), "f"(v1) : "memory");
}
__device__ __forceinline__ void stcs1(float* p, float v0) {
    asm volatile("st.global.cs.f32 [%0], %1;" :: "l"(p), "f"(v0) : "memory");
}
__device__ __forceinline__ uint4 pack8_f16(const float4& a, const float4& b) {
    union { __half2 h[4]; uint4 u; } r;
    r.h[0] = __floats2half2_rn(a.x, a.y);
    r.h[1] = __floats2half2_rn(a.z, a.w);
    r.h[2] = __floats2half2_rn(b.x, b.y);
    r.h[3] = __floats2half2_rn(b.z, b.w);
    return r.u;
}

// ---------------------------------------------------------------------------
// Fused prep kernel (R12: vectorized, __ldcs on fp32 inputs).
// ---------------------------------------------------------------------------
#define BMT 128
#define BNT 128
#define BKT 64
#define NSTAGES 3

__global__ void prep_kernel(const float* __restrict__ x,
                            const float* __restrict__ W,
                            const float* __restrict__ coeff,
                            const int* __restrict__ mole_sizes,
                            int E, int B,
                            long long n8, long long OI8, int xb, int wb) {
    int bid = blockIdx.x;
    if (bid < xb) {
        long long idx = (long long)bid * blockDim.x + threadIdx.x;
        if (idx >= n8) return;
        float4 v0 = __ldcs(reinterpret_cast<const float4*>(x) + idx * 2 + 0);
        float4 v1 = __ldcs(reinterpret_cast<const float4*>(x) + idx * 2 + 1);
        reinterpret_cast<uint4*>(g_xh)[idx] = pack8_f16(v0, v1);
        return;
    }
    if (bid < xb + wb) {
        long long idx = (long long)(bid - xb) * blockDim.x + threadIdx.x;
        __shared__ float sc[MAX_COEFF];
        int ncoef = B * E;
        for (int i = threadIdx.x; i < ncoef; i += blockDim.x) sc[i] = coeff[i];
        __syncthreads();
        if (idx >= OI8) return;

        float4 w0[8], w1[8];
#pragma unroll
        for (int e = 0; e < 8; e++) {
            if (e < E) {
                w0[e] = __ldcs(reinterpret_cast<const float4*>(W)
                               + ((long long)e * OI8 + idx) * 2 + 0);
                w1[e] = __ldcs(reinterpret_cast<const float4*>(W)
                               + ((long long)e * OI8 + idx) * 2 + 1);
            } else {
                w0[e] = make_float4(0.f, 0.f, 0.f, 0.f);
                w1[e] = make_float4(0.f, 0.f, 0.f, 0.f);
            }
        }
        for (int b = 0; b < B; b++) {
            float4 a0 = make_float4(0.f, 0.f, 0.f, 0.f);
            float4 a1 = make_float4(0.f, 0.f, 0.f, 0.f);
#pragma unroll
            for (int e = 0; e < 8; e++) {
                if (e < E) {
                    float c = sc[b * E + e];
                    a0.x += c * w0[e].x; a0.y += c * w0[e].y;
                    a0.z += c * w0[e].z; a0.w += c * w0[e].w;
                    a1.x += c * w1[e].x; a1.y += c * w1[e].y;
                    a1.z += c * w1[e].z; a1.w += c * w1[e].w;
                }
            }
            reinterpret_cast<uint4*>(g_wh)[(long long)b * OI8 + idx] =
                pack8_f16(a0, a1);
        }
        return;
    }
    // tile table
    if (threadIdx.x == 0) {
        int cnt = 0, off = 0;
        for (int b = 0; b < B; b++) {
            int sz = mole_sizes[b];
            for (int r = 0; r < sz; r += BMT) {
                if (cnt < MAX_TILES) {
                    g_tile_row[cnt] = off + r;
                    g_tile_rows[cnt] = (sz - r) < BMT ? (sz - r) : BMT;
                    g_tile_seg[cnt] = b;
                }
                cnt++;
            }
            off += sz;
        }
        g_tile_cnt = cnt < MAX_TILES ? cnt : MAX_TILES;
    }
}

// ---------------------------------------------------------------------------
// Persistent GEMM: fp16 mma.sync, item = (row tile 128) x (col block 128),
// BKT=64, 3 smem stages, continuous prefetch stream across items.
// 128 threads (4 warps 64x64), 2 CTAs/SM.
// Tile = 128 rows x 128B (8 x 16B chunks), swizzle chunk' = c ^ (r & 7).
// ---------------------------------------------------------------------------
#define TILE_B   16384
#define STAGE_B  (2 * TILE_B)
#define O_A 0
#define O_B TILE_B
#define GEMM_SMEM (NSTAGES * STAGE_B)
#define GTHREADS 128
#define PERSIST_GRID 304

__device__ __forceinline__ uint32_t swz8(uint32_t r, uint32_t c) {
    return r * 128u + ((c ^ (r & 7u)) << 4);
}

// one tile = 128 rows x 8 x 16B = 1024 cp16; 128 threads -> 8 each
__device__ __forceinline__ void load_tile(uint32_t sdst, const char* gsrc,
                                          long long pitch, int nvalid, int tid) {
#pragma unroll
    for (int t = 0; t < 8; t++) {
        int idx = tid + t * GTHREADS;
        int r = idx >> 3;
        int c = idx & 7;
        uint32_t soff = swz8((uint32_t)r, (uint32_t)c);
        int rr = r < nvalid ? r : 0;
        int sz = r < nvalid ? 16 : 0;
        cp16(sdst + soff, gsrc + (long long)rr * pitch + c * 16, sz);
    }
}

__global__ __launch_bounds__(GTHREADS, 2)
void gemm_kernel(const float* __restrict__ bias,
                 float* __restrict__ y,
                 int I, int O) {
    extern __shared__ __align__(1024) char smem[];
    uint32_t sm0 = smem_u32(smem);

    const int tid  = threadIdx.x;
    const int lane = tid & 31;
    const int wid  = tid >> 5;
    const int warp_m = wid & 1;     // 2 x 64 rows
    const int warp_n = wid >> 1;    // 2 x 64 cols

    const long long OI = (long long)O * I;
    const long long pitch = (long long)I * 2;   // bytes per row
    const char* xh_base = (const char*)g_xh;
    const int ncb = (O + BNT - 1) / BNT;
    const int nch = I / BKT;                    // 16
    const int total = g_tile_cnt * ncb;
    const int G = gridDim.x;

    // ---- prefetch stream state ----
    int pf_q = blockIdx.x;
    int pf_c = 0;
    const char* pf_xa = xh_base;
    const char* pf_wa = (const char*)g_wh;
    int pf_nrows = 0, pf_ncols = 0;
    if (pf_q < total) {
        int t = pf_q / ncb, cb = pf_q - t * ncb;
        pf_nrows = g_tile_rows[t];
        int c0 = cb * BNT;
        pf_ncols = O - c0; if (pf_ncols > BNT) pf_ncols = BNT;
        pf_xa = xh_base + (long long)g_tile_row[t] * pitch;
        pf_wa = (const char*)(g_wh + (long long)g_tile_seg[t] * OI)
                + (long long)c0 * pitch;
    }
    uint32_t pf_stage = sm0;

    #define ISSUE_PF() do {                                                  \
        if (pf_q < total) {                                                  \
            long long kb = (long long)pf_c * 128;                            \
            load_tile(pf_stage + O_A, pf_xa + kb, pitch, pf_nrows, tid);     \
            load_tile(pf_stage + O_B, pf_wa + kb, pitch, pf_ncols, tid);     \
            pf_c++;                                                          \
            if (pf_c == nch) {                                               \
                pf_c = 0; pf_q += G;                                         \
                if (pf_q < total) {                                          \
                    int t_ = pf_q / ncb, cb_ = pf_q - t_ * ncb;              \
                    pf_nrows = g_tile_rows[t_];                              \
                    int c0_ = cb_ * BNT;                                     \
                    pf_ncols = O - c0_; if (pf_ncols > BNT) pf_ncols = BNT;  \
                    pf_xa = xh_base + (long long)g_tile_row[t_] * pitch;     \
                    pf_wa = (const char*)(g_wh                               \
                              + (long long)g_tile_seg[t_] * OI)              \
                            + (long long)c0_ * pitch;                       \
                }                                                            \
            }                                                                \
        }                                                                    \
        CP_COMMIT();                                                         \
        pf_stage += STAGE_B;                                                 \
        if (pf_stage == sm0 + NSTAGES * STAGE_B) pf_stage = sm0;             \
    } while (0)

    // prologue: 2 chunks in flight
    ISSUE_PF();
    ISSUE_PF();

    uint32_t cons_stage = sm0;

    const int rlA  = ((lane >> 3) & 1) * 8 + (lane & 7);
    const int chiA = lane >> 4;
    const int rlB  = ((lane >> 4) & 1) * 8 + (lane & 7);
    const int chiB = (lane >> 3) & 1;

    for (int q = blockIdx.x; q < total; q += G) {
        int t  = q / ncb, cb = q - t * ncb;
        int row0  = g_tile_row[t];
        int nrows = g_tile_rows[t];
        int col0  = cb * BNT;
        int ncols = O - col0; if (ncols > BNT) ncols = BNT;

        float acc[4][8][4];
#pragma unroll
        for (int mi = 0; mi < 4; mi++)
#pragma unroll
            for (int nj = 0; nj < 8; nj++)
#pragma unroll
                for (int p = 0; p < 4; p++) acc[mi][nj][p] = 0.f;

        for (int c = 0; c < nch; c++) {
            CP_WAIT(1);
            __syncthreads();
            ISSUE_PF();

            uint32_t sb = cons_stage;
            cons_stage += STAGE_B;
            if (cons_stage == sm0 + NSTAGES * STAGE_B) cons_stage = sm0;

#pragma unroll
            for (int ks = 0; ks < 4; ks++) {       // 4 x k16 per 64-chunk
                uint32_t a[4][4], b[4][4];
#pragma unroll
                for (int mi = 0; mi < 4; mi++) {
                    uint32_t r = (uint32_t)(warp_m * 64 + mi * 16 + rlA);
                    ldm4(a[mi], sb + O_A + swz8(r, (uint32_t)(ks * 2 + chiA)));
                }
#pragma unroll
                for (int g = 0; g < 4; g++) {
                    uint32_t r = (uint32_t)(warp_n * 64 + g * 16 + rlB);
                    ldm4(b[g], sb + O_B + swz8(r, (uint32_t)(ks * 2 + chiB)));
                }
#pragma unroll
                for (int mi = 0; mi < 4; mi++)
#pragma unroll
                    for (int nj = 0; nj < 8; nj++) {
                        int g = nj >> 1;
                        int p = (nj & 1) * 2;
                        mma_f16(acc[mi][nj], a[mi], b[g][p], b[g][p + 1]);
                    }
            }
        }

        // epilogue (overlaps with already-inflight prefetch of next item)
#pragma unroll
        for (int mi = 0; mi < 4; mi++) {
            int rA = warp_m * 64 + mi * 16 + (lane >> 2);
            int rB = rA + 8;
#pragma unroll
            for (int nj = 0; nj < 8; nj++) {
                int cg = col0 + warp_n * 64 + nj * 8 + (lane & 3) * 2;
                int cl = cg - col0;
                bool c2 = (cl + 2 <= ncols);
                bool c1 = (cl < ncols);
                float b0 = (cg < O) ? bias[cg] : 0.f;
                float b1 = (cg + 1 < O) ? bias[cg + 1] : 0.f;
                if (rA < nrows) {
                    long long base = (long long)(row0 + rA) * O + cg;
                    if (c2) stcs2(y + base, acc[mi][nj][0] + b0, acc[mi][nj][1] + b1);
                    else if (c1) stcs1(y + base, acc[mi][nj][0] + b0);
                }
                if (rB < nrows) {
                    long long base = (long long)(row0 + rB) * O + cg;
                    if (c2) stcs2(y + base, acc[mi][nj][2] + b0, acc[mi][nj][3] + b1);
                    else if (c1) stcs1(y + base, acc[mi][nj][2] + b0);
                }
            }
        }
    }
}

// ---------------------------------------------------------------------------
// Launch
// ---------------------------------------------------------------------------
extern "C" void kernel_launch(void* const* d_in, const int* in_sizes, int n_in,
                              void* d_out, int out_size) {
    const float* x     = (const float*)d_in[0];   // [N, I]
    const float* W     = (const float*)d_in[1];   // [E, O, I]
    const float* bias  = (const float*)d_in[2];   // [O]
    const float* coeff = (const float*)d_in[3];   // [B, E]
    const int*   msize = (const int*)  d_in[4];   // [B]

    const int O = in_sizes[2];
    const int N = out_size / O;
    const int I = in_sizes[0] / N;
    const int E = in_sizes[1] / (O * I);
    const int B = in_sizes[3] / E;

    // fused prep
    {
        long long n8 = (long long)N * I / 8;
        long long OI8 = (long long)O * I / 8;
        int threads = 256;
        int xb = (int)((n8 + threads - 1) / threads);
        int wb = (int)((OI8 + threads - 1) / threads);
        prep_kernel<<<xb + wb + 1, threads>>>(x, W, coeff, msize,
                                              E, B, n8, OI8, xb, wb);
    }

    // persistent GEMM
    {
        static bool attr_set = false;
        if (!attr_set) {
            cudaFuncSetAttribute(gemm_kernel,
                                 cudaFuncAttributeMaxDynamicSharedMemorySize,
                                 GEMM_SMEM);
            attr_set = true;
        }
        int maxItems = ((N + BMT - 1) / BMT + B) * ((O + BNT - 1) / BNT);
        int grid = PERSIST_GRID < maxItems ? PERSIST_GRID : maxItems;
        gemm_kernel<<<grid, GTHREADS, GEMM_SMEM>>>(bias, (float*)d_out, I, O);
    }
}